// round 11
// baseline (speedup 1.0000x reference)
#include <cuda_runtime.h>
#include <cuda_fp16.h>
#include <cstdint>

// ---------------- problem dims ----------------
#define DIM_M 8192
#define DIM_N 16384
#define DIM_K 4096

#define BM 256
#define BN 128
#define BK 128
#define STAGES 2
#define KT (DIM_K / BK)      // 32
#define MT2 (DIM_M / BM)     // 32
#define NT2 (DIM_N / BN)     // 128
#define GM 16                // supertile: m-tiles per group

#define STAGE_BYTES ((BM * BK + BN * BK) * 2)   // A 64K + B 32K fp16 = 98304
#define SMEM_TOTAL (STAGES * STAGE_BYTES)       // 196608

// ---------------- device scratch (no allocs allowed) ----------------
__device__ __align__(1024) __half g_x_h[(size_t)DIM_M * DIM_K];   // 64 MB
__device__ __align__(1024) __half g_w_h[(size_t)DIM_N * DIM_K];   // 128 MB

// ---------------- PTX helpers (plain-compute_103-safe) ----------------
__device__ __forceinline__ uint32_t smem_u32(const void* p) {
    uint32_t a;
    asm("{ .reg .u64 t; cvta.to.shared.u64 t, %1; cvt.u32.u64 %0, t; }" : "=r"(a) : "l"(p));
    return a;
}

__device__ __forceinline__ void cp_async16(uint32_t saddr, const void* gaddr) {
    asm volatile("cp.async.cg.shared.global [%0], [%1], 16;" :: "r"(saddr), "l"(gaddr) : "memory");
}
#define CP_COMMIT()   asm volatile("cp.async.commit_group;" ::: "memory")
#define CP_WAIT_ALL() asm volatile("cp.async.wait_group 0;" ::: "memory")

#define LDMATRIX_X4(r0, r1, r2, r3, addr)                                              \
    asm volatile("ldmatrix.sync.aligned.m8n8.x4.shared.b16 {%0,%1,%2,%3}, [%4];"        \
                 : "=r"(r0), "=r"(r1), "=r"(r2), "=r"(r3) : "r"(addr))

#define MMA_16816(c, a, b)                                                             \
    asm volatile("mma.sync.aligned.m16n8k16.row.col.f32.f16.f16.f32 "                  \
                 "{%0,%1,%2,%3}, {%4,%5,%6,%7}, {%8,%9}, {%0,%1,%2,%3};"               \
                 : "+f"((c)[0]), "+f"((c)[1]), "+f"((c)[2]), "+f"((c)[3])              \
                 : "r"((a)[0]), "r"((a)[1]), "r"((a)[2]), "r"((a)[3]),                 \
                   "r"((b)[0]), "r"((b)[1]))

// ---------------- merged conversion kernel (8 elements / thread, grid-stride) ----------------
// groups [0, n8x) -> x * scale -> g_x_h ; groups [n8x, n8x+n8w) -> w -> g_w_h
__global__ void conv_all_f16(const float* __restrict__ x, const float* __restrict__ w,
                             const float* __restrict__ scale,
                             __half* __restrict__ xh, __half* __restrict__ wh,
                             int n8x, int n8tot) {
    const float s = scale[0];
    for (int i = blockIdx.x * blockDim.x + threadIdx.x; i < n8tot; i += gridDim.x * blockDim.x) {
        union { __half h[8]; uint4 u; } H;
        if (i < n8x) {
            float4 v0 = reinterpret_cast<const float4*>(x)[2 * (size_t)i];
            float4 v1 = reinterpret_cast<const float4*>(x)[2 * (size_t)i + 1];
            H.h[0] = __float2half(v0.x * s); H.h[1] = __float2half(v0.y * s);
            H.h[2] = __float2half(v0.z * s); H.h[3] = __float2half(v0.w * s);
            H.h[4] = __float2half(v1.x * s); H.h[5] = __float2half(v1.y * s);
            H.h[6] = __float2half(v1.z * s); H.h[7] = __float2half(v1.w * s);
            reinterpret_cast<uint4*>(xh)[i] = H.u;
        } else {
            size_t j = (size_t)(i - n8x);
            float4 v0 = reinterpret_cast<const float4*>(w)[2 * j];
            float4 v1 = reinterpret_cast<const float4*>(w)[2 * j + 1];
            H.h[0] = __float2half(v0.x); H.h[1] = __float2half(v0.y);
            H.h[2] = __float2half(v0.z); H.h[3] = __float2half(v0.w);
            H.h[4] = __float2half(v1.x); H.h[5] = __float2half(v1.y);
            H.h[6] = __float2half(v1.z); H.h[7] = __float2half(v1.w);
            reinterpret_cast<uint4*>(wh)[j] = H.u;
        }
    }
}

// ---------------- main GEMM kernel (HMMA fp16 -> fp32, 64x64 warp tiles) ----------------
// smem row = 128 fp16 = 256B = 16 chunks of 16B; physical chunk = c ^ (row & 7)
__global__ void __launch_bounds__(256, 1) hmma_gemm(
    const __half* __restrict__ Ah,   // [M, K] fp16, pre-scaled
    const __half* __restrict__ Bh,   // [N, K] fp16 (W)
    const float* __restrict__ bias,  // [N]
    float* __restrict__ out)         // [M, N]
{
    extern __shared__ char smem[];
    const uint32_t sb = smem_u32(smem);
    const int tid = threadIdx.x;
    const int wid = tid >> 5;
    const int lane = tid & 31;
    const int warp_m = wid & 3;   // 0..3 -> 64-row slabs
    const int warp_n = wid >> 2;  // 0..1 -> 64-col slabs

    // supertile raster: GM m-tiles fastest, then n, then group
    const int bid = blockIdx.x;
    const int mt = (bid / (GM * NT2)) * GM + (bid % GM);
    const int nt = (bid / GM) % NT2;
    const int m0 = mt * BM;
    const int n0 = nt * BN;

    // one slice = 1/4 of a stage's loads: A 1024 chunks + B 512 chunks => 6 cp.async/thread
    auto load_slice = [&](int s, int kt, int sl) {
        const uint32_t sA = sb + s * STAGE_BYTES;
        const uint32_t sB = sA + BM * BK * 2;
        const __half* gA = Ah + (size_t)m0 * DIM_K + (size_t)kt * BK;
        const __half* gB = Bh + (size_t)n0 * DIM_K + (size_t)kt * BK;
#pragma unroll
        for (int i = 0; i < 4; i++) {                 // A: slice of 1024 chunks
            int ch = sl * 1024 + i * 256 + tid;
            int row = ch >> 4, c = ch & 15;
            cp_async16(sA + row * 256 + ((c ^ (row & 7)) << 4),
                       gA + (size_t)row * DIM_K + c * 8);
        }
#pragma unroll
        for (int i = 0; i < 2; i++) {                 // B: slice of 512 chunks
            int ch = sl * 512 + i * 256 + tid;
            int row = ch >> 4, c = ch & 15;
            cp_async16(sB + row * 256 + ((c ^ (row & 7)) << 4),
                       gB + (size_t)row * DIM_K + c * 8);
        }
    };

    float acc[4][8][4];
#pragma unroll
    for (int i = 0; i < 4; i++)
#pragma unroll
        for (int j = 0; j < 8; j++)
#pragma unroll
            for (int q = 0; q < 4; q++) acc[i][j][q] = 0.0f;

    // prologue: stage 0 fully in flight
#pragma unroll
    for (int sl = 0; sl < 4; sl++) load_slice(0, 0, sl);
    CP_COMMIT();

    for (int kt = 0; kt < KT; kt++) {
        const int stage = kt & 1;
        CP_WAIT_ALL();        // group kt complete
        __syncthreads();      // publish stage kt; all reads of stage kt-1 done

        const uint32_t sA = sb + stage * STAGE_BYTES;
        const uint32_t sB = sA + BM * BK * 2;
        const bool more = (kt + 1 < KT);

#pragma unroll
        for (int ks = 0; ks < 8; ks++) {   // 8 x k16 per BK=128 chunk
            // A fragments: 4 m16 tiles (64 rows)
            uint32_t a[4][4];
#pragma unroll
            for (int mi = 0; mi < 4; mi++) {
                int row = warp_m * 64 + mi * 16 + (lane & 15);
                int chunk = ks * 2 + (lane >> 4);
                uint32_t addr = sA + row * 256 + ((chunk ^ (row & 7)) << 4);
                LDMATRIX_X4(a[mi][0], a[mi][1], a[mi][2], a[mi][3], addr);
            }
            // B fragments: 8 n8 tiles (64 cols), 2 per ldmatrix.x4
            uint32_t b[8][2];
#pragma unroll
            for (int p = 0; p < 4; p++) {
                int lane8 = lane & 7;
                int g = lane >> 3;
                int rowb = warp_n * 64 + p * 16 + ((g & 2) ? 8 : 0) + lane8;
                int chunk = ks * 2 + (g & 1);
                uint32_t addr = sB + rowb * 256 + ((chunk ^ (rowb & 7)) << 4);
                LDMATRIX_X4(b[2 * p][0], b[2 * p][1], b[2 * p + 1][0], b[2 * p + 1][1], addr);
            }
#pragma unroll
            for (int mi = 0; mi < 4; mi++)
#pragma unroll
                for (int ni = 0; ni < 8; ni++)
                    MMA_16816(acc[mi][ni], a[mi], b[ni]);

            // spread next-chunk loads at ks = 0,2,4,6 (spaced to de-cluster
            // cp.async smem writes vs the LDSM read stream); last slice still
            // lands >= 1024 cyc (ks 7 + boundary) before its consumption.
            if ((ks & 1) == 0 && more) load_slice(stage ^ 1, kt + 1, ks >> 1);
        }
        CP_COMMIT();          // one group per chunk
    }

    // -------- epilogue: direct register -> gmem (float2), + bias --------
    float2 bv[8];
#pragma unroll
    for (int ni = 0; ni < 8; ni++) {
        int col = n0 + warp_n * 64 + ni * 8 + 2 * (lane & 3);
        bv[ni] = *reinterpret_cast<const float2*>(bias + col);
    }
#pragma unroll
    for (int mi = 0; mi < 4; mi++) {
        size_t r0 = (size_t)(m0 + warp_m * 64 + mi * 16 + (lane >> 2));
        size_t r1 = r0 + 8;
#pragma unroll
        for (int ni = 0; ni < 8; ni++) {
            int col = n0 + warp_n * 64 + ni * 8 + 2 * (lane & 3);
            float2 v0 = make_float2(acc[mi][ni][0] + bv[ni].x, acc[mi][ni][1] + bv[ni].y);
            float2 v1 = make_float2(acc[mi][ni][2] + bv[ni].x, acc[mi][ni][3] + bv[ni].y);
            *reinterpret_cast<float2*>(out + r0 * DIM_N + col) = v0;
            *reinterpret_cast<float2*>(out + r1 * DIM_N + col) = v1;
        }
    }
}

// ---------------- host launch ----------------
extern "C" void kernel_launch(void* const* d_in, const int* in_sizes, int n_in,
                              void* d_out, int out_size) {
    const float* x     = (const float*)d_in[0];
    const float* w     = (const float*)d_in[1];
    const float* scale = (const float*)d_in[2];
    const float* bias  = (const float*)d_in[3];
    float* out = (float*)d_out;

    void *p_xh = nullptr, *p_wh = nullptr;
    cudaGetSymbolAddress(&p_xh, g_x_h);
    cudaGetSymbolAddress(&p_wh, g_w_h);

    const int n8x = DIM_M * DIM_K / 8;                      // 4M groups
    const int n8w = (int)((size_t)DIM_N * DIM_K / 8);       // 8M groups
    const int n8tot = n8x + n8w;
    // 512-thread blocks, ~8 grid-stride iterations/thread for deep MLP
    const int cta = 512;
    int blocks = (n8tot + cta * 8 - 1) / (cta * 8);
    conv_all_f16<<<blocks, cta>>>(x, w, scale, (__half*)p_xh, (__half*)p_wh, n8x, n8tot);

    cudaFuncSetAttribute(hmma_gemm, cudaFuncAttributeMaxDynamicSharedMemorySize, SMEM_TOTAL);
    hmma_gemm<<<MT2 * NT2, 256, SMEM_TOTAL>>>((const __half*)p_xh, (const __half*)p_wh, bias, out);
}

// round 12
// speedup vs baseline: 1.0650x; 1.0650x over previous
#include <cuda_runtime.h>
#include <cuda_fp16.h>
#include <cstdint>

// ---------------- problem dims ----------------
#define DIM_M 8192
#define DIM_N 16384
#define DIM_K 4096

#define BM 256
#define BN 128
#define BK 128
#define STAGES 2
#define KT (DIM_K / BK)      // 32
#define MT2 (DIM_M / BM)     // 32
#define NT2 (DIM_N / BN)     // 128
#define GM 16                // supertile: m-tiles per group

#define STAGE_BYTES ((BM * BK + BN * BK) * 2)   // A 64K + B 32K fp16 = 98304
#define SMEM_TOTAL (STAGES * STAGE_BYTES)       // 196608

// ---------------- device scratch (no allocs allowed) ----------------
__device__ __align__(1024) __half g_x_h[(size_t)DIM_M * DIM_K];   // 64 MB
__device__ __align__(1024) __half g_w_h[(size_t)DIM_N * DIM_K];   // 128 MB

// ---------------- PTX helpers (plain-compute_103-safe) ----------------
__device__ __forceinline__ uint32_t smem_u32(const void* p) {
    uint32_t a;
    asm("{ .reg .u64 t; cvta.to.shared.u64 t, %1; cvt.u32.u64 %0, t; }" : "=r"(a) : "l"(p));
    return a;
}

__device__ __forceinline__ void cp_async16(uint32_t saddr, const void* gaddr) {
    asm volatile("cp.async.cg.shared.global [%0], [%1], 16;" :: "r"(saddr), "l"(gaddr) : "memory");
}
#define CP_COMMIT()   asm volatile("cp.async.commit_group;" ::: "memory")
#define CP_WAIT_ALL() asm volatile("cp.async.wait_group 0;" ::: "memory")

#define LDMATRIX_X4(r0, r1, r2, r3, addr)                                              \
    asm volatile("ldmatrix.sync.aligned.m8n8.x4.shared.b16 {%0,%1,%2,%3}, [%4];"        \
                 : "=r"(r0), "=r"(r1), "=r"(r2), "=r"(r3) : "r"(addr))

#define MMA_16816(c, a, b)                                                             \
    asm volatile("mma.sync.aligned.m16n8k16.row.col.f32.f16.f16.f32 "                  \
                 "{%0,%1,%2,%3}, {%4,%5,%6,%7}, {%8,%9}, {%0,%1,%2,%3};"               \
                 : "+f"((c)[0]), "+f"((c)[1]), "+f"((c)[2]), "+f"((c)[3])              \
                 : "r"((a)[0]), "r"((a)[1]), "r"((a)[2]), "r"((a)[3]),                 \
                   "r"((b)[0]), "r"((b)[1]))

// ---------------- merged conversion kernel (8 elements / thread, grid-stride) ----------------
// groups [0, n8x) -> x * scale -> g_x_h ; groups [n8x, n8x+n8w) -> w -> g_w_h
__global__ void conv_all_f16(const float* __restrict__ x, const float* __restrict__ w,
                             const float* __restrict__ scale,
                             __half* __restrict__ xh, __half* __restrict__ wh,
                             int n8x, int n8tot) {
    const float s = scale[0];
    for (int i = blockIdx.x * blockDim.x + threadIdx.x; i < n8tot; i += gridDim.x * blockDim.x) {
        union { __half h[8]; uint4 u; } H;
        if (i < n8x) {
            float4 v0 = reinterpret_cast<const float4*>(x)[2 * (size_t)i];
            float4 v1 = reinterpret_cast<const float4*>(x)[2 * (size_t)i + 1];
            H.h[0] = __float2half(v0.x * s); H.h[1] = __float2half(v0.y * s);
            H.h[2] = __float2half(v0.z * s); H.h[3] = __float2half(v0.w * s);
            H.h[4] = __float2half(v1.x * s); H.h[5] = __float2half(v1.y * s);
            H.h[6] = __float2half(v1.z * s); H.h[7] = __float2half(v1.w * s);
            reinterpret_cast<uint4*>(xh)[i] = H.u;
        } else {
            size_t j = (size_t)(i - n8x);
            float4 v0 = reinterpret_cast<const float4*>(w)[2 * j];
            float4 v1 = reinterpret_cast<const float4*>(w)[2 * j + 1];
            H.h[0] = __float2half(v0.x); H.h[1] = __float2half(v0.y);
            H.h[2] = __float2half(v0.z); H.h[3] = __float2half(v0.w);
            H.h[4] = __float2half(v1.x); H.h[5] = __float2half(v1.y);
            H.h[6] = __float2half(v1.z); H.h[7] = __float2half(v1.w);
            reinterpret_cast<uint4*>(wh)[j] = H.u;
        }
    }
}

// ---------------- main GEMM kernel (HMMA fp16 -> fp32, 64x64 warp tiles) ----------------
// smem row = 128 fp16 = 256B = 16 chunks of 16B; physical chunk = c ^ (row & 7)
__global__ void __launch_bounds__(256, 1) hmma_gemm(
    const __half* __restrict__ Ah,   // [M, K] fp16, pre-scaled
    const __half* __restrict__ Bh,   // [N, K] fp16 (W)
    const float* __restrict__ bias,  // [N]
    float* __restrict__ out)         // [M, N]
{
    extern __shared__ char smem[];
    const uint32_t sb = smem_u32(smem);
    const int tid = threadIdx.x;
    const int wid = tid >> 5;
    const int lane = tid & 31;
    const int warp_m = wid & 3;   // 0..3 -> 64-row slabs
    const int warp_n = wid >> 2;  // 0..1 -> 64-col slabs

    // supertile raster: GM m-tiles fastest, then n, then group
    const int bid = blockIdx.x;
    const int mt = (bid / (GM * NT2)) * GM + (bid % GM);
    const int nt = (bid / GM) % NT2;
    const int m0 = mt * BM;
    const int n0 = nt * BN;

    // one slice = 1/4 of a stage's loads: A 1024 chunks + B 512 chunks => 6 cp.async/thread
    auto load_slice = [&](int s, int kt, int sl) {
        const uint32_t sA = sb + s * STAGE_BYTES;
        const uint32_t sB = sA + BM * BK * 2;
        const __half* gA = Ah + (size_t)m0 * DIM_K + (size_t)kt * BK;
        const __half* gB = Bh + (size_t)n0 * DIM_K + (size_t)kt * BK;
#pragma unroll
        for (int i = 0; i < 4; i++) {                 // A: slice of 1024 chunks
            int ch = sl * 1024 + i * 256 + tid;
            int row = ch >> 4, c = ch & 15;
            cp_async16(sA + row * 256 + ((c ^ (row & 7)) << 4),
                       gA + (size_t)row * DIM_K + c * 8);
        }
#pragma unroll
        for (int i = 0; i < 2; i++) {                 // B: slice of 512 chunks
            int ch = sl * 512 + i * 256 + tid;
            int row = ch >> 4, c = ch & 15;
            cp_async16(sB + row * 256 + ((c ^ (row & 7)) << 4),
                       gB + (size_t)row * DIM_K + c * 8);
        }
    };

    float acc[4][8][4];
#pragma unroll
    for (int i = 0; i < 4; i++)
#pragma unroll
        for (int j = 0; j < 8; j++)
#pragma unroll
            for (int q = 0; q < 4; q++) acc[i][j][q] = 0.0f;

    // prologue: stage 0 fully in flight
#pragma unroll
    for (int sl = 0; sl < 4; sl++) load_slice(0, 0, sl);
    CP_COMMIT();

    for (int kt = 0; kt < KT; kt++) {
        const int stage = kt & 1;
        CP_WAIT_ALL();        // group kt complete
        __syncthreads();      // publish stage kt; all reads of stage kt-1 done

        const uint32_t sA = sb + stage * STAGE_BYTES;
        const uint32_t sB = sA + BM * BK * 2;
        const bool more = (kt + 1 < KT);

#pragma unroll
        for (int ks = 0; ks < 8; ks++) {   // 8 x k16 per BK=128 chunk
            // A fragments: 4 m16 tiles (64 rows)
            uint32_t a[4][4];
#pragma unroll
            for (int mi = 0; mi < 4; mi++) {
                int row = warp_m * 64 + mi * 16 + (lane & 15);
                int chunk = ks * 2 + (lane >> 4);
                uint32_t addr = sA + row * 256 + ((chunk ^ (row & 7)) << 4);
                LDMATRIX_X4(a[mi][0], a[mi][1], a[mi][2], a[mi][3], addr);
            }
            // B fragments: 8 n8 tiles (64 cols), 2 per ldmatrix.x4
            uint32_t b[8][2];
#pragma unroll
            for (int p = 0; p < 4; p++) {
                int lane8 = lane & 7;
                int g = lane >> 3;
                int rowb = warp_n * 64 + p * 16 + ((g & 2) ? 8 : 0) + lane8;
                int chunk = ks * 2 + (g & 1);
                uint32_t addr = sB + rowb * 256 + ((chunk ^ (rowb & 7)) << 4);
                LDMATRIX_X4(b[2 * p][0], b[2 * p][1], b[2 * p + 1][0], b[2 * p + 1][1], addr);
            }
#pragma unroll
            for (int mi = 0; mi < 4; mi++)
#pragma unroll
                for (int ni = 0; ni < 8; ni++)
                    MMA_16816(acc[mi][ni], a[mi], b[ni]);

            // issue next-chunk loads as EARLY as possible: 2 slices at ks=0,
            // 2 slices at ks=1 (R11 showed completion latency, not SMEM-write
            // contention, binds the chunk boundary).
            if (ks < 2 && more) {
                load_slice(stage ^ 1, kt + 1, 2 * ks);
                load_slice(stage ^ 1, kt + 1, 2 * ks + 1);
            }
        }
        CP_COMMIT();          // one group per chunk
    }

    // -------- epilogue: direct register -> gmem (float2), + bias --------
    float2 bv[8];
#pragma unroll
    for (int ni = 0; ni < 8; ni++) {
        int col = n0 + warp_n * 64 + ni * 8 + 2 * (lane & 3);
        bv[ni] = *reinterpret_cast<const float2*>(bias + col);
    }
#pragma unroll
    for (int mi = 0; mi < 4; mi++) {
        size_t r0 = (size_t)(m0 + warp_m * 64 + mi * 16 + (lane >> 2));
        size_t r1 = r0 + 8;
#pragma unroll
        for (int ni = 0; ni < 8; ni++) {
            int col = n0 + warp_n * 64 + ni * 8 + 2 * (lane & 3);
            float2 v0 = make_float2(acc[mi][ni][0] + bv[ni].x, acc[mi][ni][1] + bv[ni].y);
            float2 v1 = make_float2(acc[mi][ni][2] + bv[ni].x, acc[mi][ni][3] + bv[ni].y);
            *reinterpret_cast<float2*>(out + r0 * DIM_N + col) = v0;
            *reinterpret_cast<float2*>(out + r1 * DIM_N + col) = v1;
        }
    }
}

// ---------------- host launch ----------------
extern "C" void kernel_launch(void* const* d_in, const int* in_sizes, int n_in,
                              void* d_out, int out_size) {
    const float* x     = (const float*)d_in[0];
    const float* w     = (const float*)d_in[1];
    const float* scale = (const float*)d_in[2];
    const float* bias  = (const float*)d_in[3];
    float* out = (float*)d_out;

    void *p_xh = nullptr, *p_wh = nullptr;
    cudaGetSymbolAddress(&p_xh, g_x_h);
    cudaGetSymbolAddress(&p_wh, g_w_h);

    const int n8x = DIM_M * DIM_K / 8;                      // 4M groups
    const int n8w = (int)((size_t)DIM_N * DIM_K / 8);       // 8M groups
    const int n8tot = n8x + n8w;
    // grid-stride, ~4 iterations/thread (R10 proven config)
    const int cta = 256;
    int blocks = (n8tot + cta * 4 - 1) / (cta * 4);
    conv_all_f16<<<blocks, cta>>>(x, w, scale, (__half*)p_xh, (__half*)p_wh, n8x, n8tot);

    cudaFuncSetAttribute(hmma_gemm, cudaFuncAttributeMaxDynamicSharedMemorySize, SMEM_TOTAL);
    hmma_gemm<<<MT2 * NT2, 256, SMEM_TOTAL>>>((const __half*)p_xh, (const __half*)p_wh, bias, out);
}

// round 13
// speedup vs baseline: 1.1296x; 1.0607x over previous
#include <cuda_runtime.h>
#include <cuda_fp16.h>
#include <cstdint>

// ---------------- problem dims ----------------
#define DIM_M 8192
#define DIM_N 16384
#define DIM_K 4096

#define BM 256
#define BN 128
#define BK 64
#define NSTAGE 4
#define KT2 (DIM_K / BK)     // 64 chunks
#define MT2 (DIM_M / BM)     // 32
#define NT2 (DIM_N / BN)     // 128
#define GM 16                // supertile: m-tiles per group

#define STAGE_BYTES ((BM * BK + BN * BK) * 2)   // A 32K + B 16K = 49152
#define MBAR_OFF (NSTAGE * STAGE_BYTES)         // 196608
#define SMEM_TOTAL (MBAR_OFF + 128)             // + barrier block

// ---------------- device scratch (no allocs allowed) ----------------
__device__ __align__(1024) __half g_x_h[(size_t)DIM_M * DIM_K];   // 64 MB
__device__ __align__(1024) __half g_w_h[(size_t)DIM_N * DIM_K];   // 128 MB

// ---------------- PTX helpers (plain-compute_103-safe, all sm_80-era) ----------------
__device__ __forceinline__ uint32_t smem_u32(const void* p) {
    uint32_t a;
    asm("{ .reg .u64 t; cvta.to.shared.u64 t, %1; cvt.u32.u64 %0, t; }" : "=r"(a) : "l"(p));
    return a;
}

__device__ __forceinline__ void cp_async16(uint32_t saddr, const void* gaddr) {
    asm volatile("cp.async.cg.shared.global [%0], [%1], 16;" :: "r"(saddr), "l"(gaddr) : "memory");
}

#define MBAR_INIT(addr, cnt) \
    asm volatile("mbarrier.init.shared.b64 [%0], %1;" :: "r"(addr), "r"(cnt) : "memory")

#define MBAR_ARRIVE(addr) \
    asm volatile("mbarrier.arrive.shared.b64 _, [%0];" :: "r"(addr) : "memory")

// async arrive when all of this thread's prior cp.asyncs complete (.noinc: counts
// against the initialized expected count)
#define CPASYNC_MBAR_ARRIVE(addr) \
    asm volatile("cp.async.mbarrier.arrive.noinc.shared.b64 [%0];" :: "r"(addr) : "memory")

#define MBAR_WAIT(addr, parity) do {                                                    \
    uint32_t _m = (addr), _p = (parity), _d;                                            \
    asm volatile(                                                                       \
        "{\n\t.reg .pred p;\n\t"                                                        \
        "mbarrier.try_wait.parity.shared.b64 p, [%1], %2;\n\t"                          \
        "selp.b32 %0, 1, 0, p;\n\t}"                                                    \
        : "=r"(_d) : "r"(_m), "r"(_p) : "memory");                                      \
    if (!_d) {                                                                          \
        asm volatile(                                                                   \
            "{\n\t.reg .pred P1;\n\t"                                                   \
            "WL_%=:\n\t"                                                                \
            "mbarrier.try_wait.parity.shared.b64 P1, [%0], %1;\n\t"                     \
            "@P1 bra.uni WD_%=;\n\t"                                                    \
            "bra.uni WL_%=;\n\t"                                                        \
            "WD_%=:\n\t}"                                                               \
            :: "r"(_m), "r"(_p) : "memory");                                            \
    }                                                                                   \
} while (0)

#define LDMATRIX_X4(r0, r1, r2, r3, addr)                                              \
    asm volatile("ldmatrix.sync.aligned.m8n8.x4.shared.b16 {%0,%1,%2,%3}, [%4];"        \
                 : "=r"(r0), "=r"(r1), "=r"(r2), "=r"(r3) : "r"(addr))

#define MMA_16816(c, a, b)                                                             \
    asm volatile("mma.sync.aligned.m16n8k16.row.col.f32.f16.f16.f32 "                  \
                 "{%0,%1,%2,%3}, {%4,%5,%6,%7}, {%8,%9}, {%0,%1,%2,%3};"               \
                 : "+f"((c)[0]), "+f"((c)[1]), "+f"((c)[2]), "+f"((c)[3])              \
                 : "r"((a)[0]), "r"((a)[1]), "r"((a)[2]), "r"((a)[3]),                 \
                   "r"((b)[0]), "r"((b)[1]))

// ---------------- merged conversion kernel (R10 proven config) ----------------
__global__ void conv_all_f16(const float* __restrict__ x, const float* __restrict__ w,
                             const float* __restrict__ scale,
                             __half* __restrict__ xh, __half* __restrict__ wh,
                             int n8x, int n8tot) {
    const float s = scale[0];
    for (int i = blockIdx.x * blockDim.x + threadIdx.x; i < n8tot; i += gridDim.x * blockDim.x) {
        union { __half h[8]; uint4 u; } H;
        if (i < n8x) {
            float4 v0 = reinterpret_cast<const float4*>(x)[2 * (size_t)i];
            float4 v1 = reinterpret_cast<const float4*>(x)[2 * (size_t)i + 1];
            H.h[0] = __float2half(v0.x * s); H.h[1] = __float2half(v0.y * s);
            H.h[2] = __float2half(v0.z * s); H.h[3] = __float2half(v0.w * s);
            H.h[4] = __float2half(v1.x * s); H.h[5] = __float2half(v1.y * s);
            H.h[6] = __float2half(v1.z * s); H.h[7] = __float2half(v1.w * s);
            reinterpret_cast<uint4*>(xh)[i] = H.u;
        } else {
            size_t j = (size_t)(i - n8x);
            float4 v0 = reinterpret_cast<const float4*>(w)[2 * j];
            float4 v1 = reinterpret_cast<const float4*>(w)[2 * j + 1];
            H.h[0] = __float2half(v0.x); H.h[1] = __float2half(v0.y);
            H.h[2] = __float2half(v0.z); H.h[3] = __float2half(v0.w);
            H.h[4] = __float2half(v1.x); H.h[5] = __float2half(v1.y);
            H.h[6] = __float2half(v1.z); H.h[7] = __float2half(v1.w);
            reinterpret_cast<uint4*>(wh)[j] = H.u;
        }
    }
}

// ---------------- main GEMM kernel: mbarrier pipeline, 4 stages, no __syncthreads ----------------
// tile rows = 64 fp16 = 128B = 8 x 16B chunks; physical chunk = c ^ (row & 7)
__global__ void __launch_bounds__(256, 1) hmma_gemm(
    const __half* __restrict__ Ah,   // [M, K] fp16, pre-scaled
    const __half* __restrict__ Bh,   // [N, K] fp16 (W)
    const float* __restrict__ bias,  // [N]
    float* __restrict__ out)         // [M, N]
{
    extern __shared__ char smem[];
    const uint32_t sb = smem_u32(smem);
    const int tid = threadIdx.x;
    const int wid = tid >> 5;
    const int lane = tid & 31;
    const int warp_m = wid & 3;   // 0..3 -> 64-row slabs
    const int warp_n = wid >> 2;  // 0..1 -> 64-col slabs

    const uint32_t mb = sb + MBAR_OFF;        // full[s] at +16*s, empty[s] at +64+16*s
#define FULL_B(s)  (mb + 16 * (s))
#define EMPTY_B(s) (mb + 64 + 16 * (s))

    // supertile raster: GM m-tiles fastest, then n, then group
    const int bid = blockIdx.x;
    const int mt = (bid / (GM * NT2)) * GM + (bid % GM);
    const int nt = (bid / GM) % NT2;
    const int m0 = mt * BM;
    const int n0 = nt * BN;

    // per-thread loads for one BK=64 chunk: A 8 + B 4 = 12 cp.async
    auto load_chunk = [&](int s, int kt) {
        const uint32_t sA = sb + s * STAGE_BYTES;
        const uint32_t sB = sA + BM * BK * 2;
        const __half* gA = Ah + (size_t)m0 * DIM_K + (size_t)kt * BK;
        const __half* gB = Bh + (size_t)n0 * DIM_K + (size_t)kt * BK;
#pragma unroll
        for (int i = 0; i < 8; i++) {                 // A: 2048 16B-chunks
            int ch = i * 256 + tid;
            int row = ch >> 3, c = ch & 7;
            cp_async16(sA + row * 128 + ((c ^ (row & 7)) << 4),
                       gA + (size_t)row * DIM_K + c * 8);
        }
#pragma unroll
        for (int i = 0; i < 4; i++) {                 // B: 1024 16B-chunks
            int ch = i * 256 + tid;
            int row = ch >> 3, c = ch & 7;
            cp_async16(sB + row * 128 + ((c ^ (row & 7)) << 4),
                       gB + (size_t)row * DIM_K + c * 8);
        }
    };

    // init barriers
    if (tid == 0) {
#pragma unroll
        for (int s = 0; s < NSTAGE; s++) {
            MBAR_INIT(FULL_B(s), 256);
            MBAR_INIT(EMPTY_B(s), 256);
        }
    }
    __syncthreads();   // once, for init visibility

    // prologue: fill stages 0..2 (chunks 0..2)
#pragma unroll
    for (int c = 0; c < NSTAGE - 1; c++) {
        load_chunk(c, c);
        CPASYNC_MBAR_ARRIVE(FULL_B(c));
    }

    float acc[4][8][4];
#pragma unroll
    for (int i = 0; i < 4; i++)
#pragma unroll
        for (int j = 0; j < 8; j++)
#pragma unroll
            for (int q = 0; q < 4; q++) acc[i][j][q] = 0.0f;

    for (int kt = 0; kt < KT2; kt++) {
        const int s = kt & 3;
        MBAR_WAIT(FULL_B(s), (kt >> 2) & 1);

        const uint32_t sA = sb + s * STAGE_BYTES;
        const uint32_t sB = sA + BM * BK * 2;

#pragma unroll
        for (int ks = 0; ks < 4; ks++) {   // 4 x k16 per BK=64 chunk
            uint32_t a[4][4];
#pragma unroll
            for (int mi = 0; mi < 4; mi++) {
                int row = warp_m * 64 + mi * 16 + (lane & 15);
                int chunk = ks * 2 + (lane >> 4);
                uint32_t addr = sA + row * 128 + ((chunk ^ (row & 7)) << 4);
                LDMATRIX_X4(a[mi][0], a[mi][1], a[mi][2], a[mi][3], addr);
            }
            uint32_t b[8][2];
#pragma unroll
            for (int p = 0; p < 4; p++) {
                int lane8 = lane & 7;
                int g = lane >> 3;
                int rowb = warp_n * 64 + p * 16 + ((g & 2) ? 8 : 0) + lane8;
                int chunk = ks * 2 + (g & 1);
                uint32_t addr = sB + rowb * 128 + ((chunk ^ (rowb & 7)) << 4);
                LDMATRIX_X4(b[2 * p][0], b[2 * p][1], b[2 * p + 1][0], b[2 * p + 1][1], addr);
            }
#pragma unroll
            for (int mi = 0; mi < 4; mi++)
#pragma unroll
                for (int ni = 0; ni < 8; ni++)
                    MMA_16816(acc[mi][ni], a[mi], b[ni]);
        }

        // done reading stage s
        MBAR_ARRIVE(EMPTY_B(s));

        // produce chunk kt+3 into its stage (used 3 chunks from now)
        const int cp = kt + NSTAGE - 1;
        if (cp < KT2) {
            const int sp = cp & 3;
            if (cp >= NSTAGE) MBAR_WAIT(EMPTY_B(sp), ((cp >> 2) + 1) & 1);
            load_chunk(sp, cp);
            CPASYNC_MBAR_ARRIVE(FULL_B(sp));
        }
    }

    // -------- epilogue: direct register -> gmem (float2), + bias --------
    float2 bv[8];
#pragma unroll
    for (int ni = 0; ni < 8; ni++) {
        int col = n0 + warp_n * 64 + ni * 8 + 2 * (lane & 3);
        bv[ni] = *reinterpret_cast<const float2*>(bias + col);
    }
#pragma unroll
    for (int mi = 0; mi < 4; mi++) {
        size_t r0 = (size_t)(m0 + warp_m * 64 + mi * 16 + (lane >> 2));
        size_t r1 = r0 + 8;
#pragma unroll
        for (int ni = 0; ni < 8; ni++) {
            int col = n0 + warp_n * 64 + ni * 8 + 2 * (lane & 3);
            float2 v0 = make_float2(acc[mi][ni][0] + bv[ni].x, acc[mi][ni][1] + bv[ni].y);
            float2 v1 = make_float2(acc[mi][ni][2] + bv[ni].x, acc[mi][ni][3] + bv[ni].y);
            *reinterpret_cast<float2*>(out + r0 * DIM_N + col) = v0;
            *reinterpret_cast<float2*>(out + r1 * DIM_N + col) = v1;
        }
    }
}

// ---------------- host launch ----------------
extern "C" void kernel_launch(void* const* d_in, const int* in_sizes, int n_in,
                              void* d_out, int out_size) {
    const float* x     = (const float*)d_in[0];
    const float* w     = (const float*)d_in[1];
    const float* scale = (const float*)d_in[2];
    const float* bias  = (const float*)d_in[3];
    float* out = (float*)d_out;

    void *p_xh = nullptr, *p_wh = nullptr;
    cudaGetSymbolAddress(&p_xh, g_x_h);
    cudaGetSymbolAddress(&p_wh, g_w_h);

    const int n8x = DIM_M * DIM_K / 8;
    const int n8w = (int)((size_t)DIM_N * DIM_K / 8);
    const int n8tot = n8x + n8w;
    const int cta = 256;
    int blocks = (n8tot + cta * 4 - 1) / (cta * 4);
    conv_all_f16<<<blocks, cta>>>(x, w, scale, (__half*)p_xh, (__half*)p_wh, n8x, n8tot);

    cudaFuncSetAttribute(hmma_gemm, cudaFuncAttributeMaxDynamicSharedMemorySize, SMEM_TOTAL);
    hmma_gemm<<<MT2 * NT2, 256, SMEM_TOTAL>>>((const __half*)p_xh, (const __half*)p_wh, bias, out);
}